// round 14
// baseline (speedup 1.0000x reference)
#include <cuda_runtime.h>
#include <cstdint>

#define B_  8
#define C_  128
#define H_  192
#define W_  448
#define ND  49

#define TX  32
#define TY  8
#define KC  8
#define NCHUNK (C_ / KC)
#define NT  224          // 7 warps, warp = dj

#define S1_ROW 36                   // 144B rows: slot stride 9 (odd) -> conflict-free
#define S1_CH  (TY * S1_ROW)        // 288
#define S2_ROW 44                   // 176B rows: slot stride 11 (odd) -> conflict-free
#define S2_CH  ((TY + 6) * S2_ROW)  // 616
#define S1_SIZE (KC * S1_CH)        // 2304
#define S2_SIZE (KC * S2_CH)        // 4928
#define BUF_SIZE (S1_SIZE + S2_SIZE)               // 7232 floats
#define NBUF 3
#define BUF_BYTES (BUF_SIZE * 4)
#define SMEM_BYTES (NBUF * BUF_BYTES)              // 86784 B per CTA

typedef unsigned long long ull;

__device__ __forceinline__ uint32_t sptr(const void* p) {
    return (uint32_t)__cvta_generic_to_shared(p);
}
__device__ __forceinline__ void cp16s(uint32_t dst, const float* src, bool pred) {
    int bytes = pred ? 16 : 0;
    asm volatile("cp.async.cg.shared.global [%0], [%1], 16, %2;\n"
                 :: "r"(dst), "l"(src), "r"(bytes));
}
__device__ __forceinline__ void cp_commit() {
    asm volatile("cp.async.commit_group;\n" ::: "memory");
}
__device__ __forceinline__ void lds2(ull& a, ull& b, uint32_t addr) {
    asm volatile("ld.shared.v2.u64 {%0,%1}, [%2];"
                 : "=l"(a), "=l"(b) : "r"(addr));
}
__device__ __forceinline__ void fma2(ull& d, ull a, ull b) {
    asm("fma.rn.f32x2 %0, %1, %2, %0;" : "+l"(d) : "l"(a), "l"(b));
}
__device__ __forceinline__ void unpack2(float& lo, float& hi, ull v) {
    asm("mov.b64 {%0,%1}, %2;" : "=f"(lo), "=f"(hi) : "l"(v));
}
// o = (hi half of elo, lo half of ehi) -- pure register-half selection.
__device__ __forceinline__ void make_o(ull& o, ull elo, ull ehi) {
    asm("{\n\t.reg .b32 a,b,c,d;\n\t"
        "mov.b64 {a,b}, %1;\n\t"
        "mov.b64 {c,d}, %2;\n\t"
        "mov.b64 %0, {b,c};\n\t}"
        : "=l"(o) : "l"(elo), "l"(ehi));
}

__device__ __forceinline__ void load_ef(
    uint32_t a1, uint32_t a2, ull (&f)[4], ull (&e)[8])
{
    lds2(f[0], f[1], a1);
    lds2(f[2], f[3], a1 + 16);
    lds2(e[0], e[1], a2);
    lds2(e[2], e[3], a2 + 16);
    lds2(e[4], e[5], a2 + 32);
    lds2(e[6], e[7], a2 + 48);
}

__device__ __forceinline__ void compute_ch(
    ull* __restrict__ acc2, const ull (&f)[4], const ull (&e)[8])
{
    ull o[7];
#pragma unroll
    for (int t = 0; t < 7; ++t)
        make_o(o[t], e[t], e[t + 1]);
#pragma unroll
    for (int d = 0; d < 7; ++d) {
#pragma unroll
        for (int pp = 0; pp < 4; ++pp) {
            ull vp = (d & 1) ? e[(d + 1) / 2 + pp] : o[d / 2 + pp];
            fma2(acc2[d * 4 + pp], f[pp], vp);
        }
    }
}

// Full burst loader (prologue only).
__device__ __forceinline__ void load_chunk_burst(
    uint32_t s1, uint32_t s2,
    const float* __restrict__ fbase, const float* __restrict__ sbase,
    int c0, int x0, int y0, int tid)
{
    const size_t HW = (size_t)H_ * W_;
#pragma unroll
    for (int it = 0; it < 3; ++it) {
        int u = tid + it * NT;
        if (it < 2 || u < 512) {
            int c = u >> 6;
            int row = (u >> 3) & 7;
            int q = u & 7;
            const float* src = fbase + (size_t)(c0 + c) * HW + (size_t)(y0 + row) * W_ + x0 + q * 4;
            cp16s(s1 + (uint32_t)(c * S1_CH + row * S1_ROW + q * 4) * 4, src, true);
        }
    }
    const int row = tid >> 4;
    const int q   = tid & 15;
    if (q < 11) {
        const int gy = y0 - 3 + row;
        const int gx = x0 - 4 + q * 4;
        const bool p = (gy >= 0) && (gy < H_) && (gx >= 0) && (gx < W_);
        const int gyc = gy < 0 ? 0 : (gy >= H_ ? H_ - 1 : gy);
        const int gxc = gx < 0 ? 0 : (gx >= W_ ? W_ - 1 : gx);
        const float* src0 = sbase + (size_t)c0 * HW + (size_t)gyc * W_ + gxc;
        uint32_t dst0 = s2 + (uint32_t)(row * S2_ROW + q * 4) * 4;
#pragma unroll
        for (int c = 0; c < KC; ++c)
            cp16s(dst0 + (uint32_t)(c * S2_CH) * 4, src0 + c * HW, p);
    }
}

__global__ void __launch_bounds__(NT, 2)
corr_kernel(const float* __restrict__ first,
            const float* __restrict__ second,
            float* __restrict__ out)
{
    extern __shared__ float smem[];
    const int tid = threadIdx.x;
    const int dj = tid >> 5;                  // warp = row displacement 0..6
    const int lane = tid & 31;
    // Conflict-free lane map: 8-lane LDS wavefront = 8 consecutive rows.
    const int tyl = lane & 7;
    const int txl = lane >> 3;
    const int xl = txl * 8;
    const int bx = blockIdx.x, by = blockIdx.y, b = blockIdx.z;
    const int x0 = bx * TX, y0 = by * TY;

    const size_t HW = (size_t)H_ * W_;
    const float* fbase = first  + (size_t)b * C_ * HW;
    const float* sbase = second + (size_t)b * C_ * HW;

    const uint32_t smem_base = sptr(smem);
    const uint32_t s1_thr = smem_base + (uint32_t)(tyl * S1_ROW + xl) * 4;
    const uint32_t s2_thr = smem_base + (uint32_t)S1_SIZE * 4
                          + (uint32_t)((tyl + dj) * S2_ROW + xl) * 4;

    // ---- persistent loader state (for interleaved issuance, chunks >= 2) ----
    // s2: this thread owns (row l2row, chunk-slot l2q) for all 8 channels.
    const int l2row = tid >> 4;
    const int l2q   = tid & 15;
    const bool l2act = (l2q < 11);
    int gy = y0 - 3 + l2row;
    int gx = x0 - 4 + l2q * 4;
    const bool p2 = l2act && (gy >= 0) && (gy < H_) && (gx >= 0) && (gx < W_);
    if (gy < 0) gy = 0; if (gy >= H_) gy = H_ - 1;
    if (gx < 0) gx = 0; if (gx >= W_) gx = W_ - 1;
    const float* src2 = sbase + (size_t)(2 * KC) * HW + (size_t)gy * W_ + gx;
    const uint32_t dst2 = (uint32_t)(S1_SIZE + l2row * S2_ROW + l2q * 4) * 4;

    // s1: three units per thread (third partially active).
    const float* src1[3];
    uint32_t dst1[3];
    bool act1[3];
#pragma unroll
    for (int i = 0; i < 3; ++i) {
        int u = tid + i * NT;
        act1[i] = (u < 512);
        int c = u >> 6;
        int row = (u >> 3) & 7;
        int q = u & 7;
        src1[i] = fbase + (size_t)(2 * KC + c) * HW + (size_t)(y0 + row) * W_ + x0 + q * 4;
        dst1[i] = (uint32_t)(c * S1_CH + row * S1_ROW + q * 4) * 4;
    }

    ull acc2[28];
#pragma unroll
    for (int i = 0; i < 28; ++i) acc2[i] = 0ull;

    // Prologue: burst-fill buffers 0 and 1.
    load_chunk_burst(smem_base, smem_base + (uint32_t)S1_SIZE * 4,
                     fbase, sbase, 0, x0, y0, tid);
    cp_commit();
    load_chunk_burst(smem_base + BUF_BYTES, smem_base + BUF_BYTES + (uint32_t)S1_SIZE * 4,
                     fbase, sbase, KC, x0, y0, tid);
    cp_commit();

    uint32_t coff = 0;   // compute buffer byte offset
    uint32_t loff = 2 * BUF_BYTES;  // load buffer byte offset

#pragma unroll 1
    for (int k = 0; k < NCHUNK; ++k) {
        if (k < NCHUNK - 1) {
            asm volatile("cp.async.wait_group 1;\n" ::: "memory");
        } else {
            asm volatile("cp.async.wait_group 0;\n" ::: "memory");
        }
        __syncthreads();   // buffer loff free, buffer coff ready

        const bool doload = (k + 2 < NCHUNK);
        uint32_t a1 = s1_thr + coff;
        uint32_t a2 = s2_thr + coff;
        const uint32_t ld2 = smem_base + loff + dst2;

        ull f0[4], e0[8], f1[4], e1[8];
        load_ef(a1, a2, f0, e0);                     // c = 0

#pragma unroll
        for (int c = 0; c < KC; c += 2) {
            a1 += S1_CH * 4; a2 += S2_CH * 4;
            load_ef(a1, a2, f1, e1);                 // c+1
            // interleave: issue s2 cp16 for chunk k+2, channel c
            if (doload && l2act)
                cp16s(ld2 + (uint32_t)(c * S2_CH) * 4, src2 + (size_t)c * HW, p2);
            // s1 units on iterations 0,1,2 (c = 0,2,4)
            if (doload && c < 6 && act1[c >> 1])
                cp16s(smem_base + loff + dst1[c >> 1], src1[c >> 1], true);
            compute_ch(acc2, f0, e0);                // c
            if (c + 2 < KC) {
                a1 += S1_CH * 4; a2 += S2_CH * 4;
                load_ef(a1, a2, f0, e0);             // c+2
            }
            if (doload && l2act)
                cp16s(ld2 + (uint32_t)((c + 1) * S2_CH) * 4, src2 + (size_t)(c + 1) * HW, p2);
            compute_ch(acc2, f1, e1);                // c+1
        }

        if (doload) {
            cp_commit();
            src2 += KC * HW;
#pragma unroll
            for (int i = 0; i < 3; ++i) src1[i] += KC * HW;
        }

        coff += BUF_BYTES;
        if (coff == NBUF * BUF_BYTES) coff = 0;
        loff += BUF_BYTES;
        if (loff == NBUF * BUF_BYTES) loff = 0;
    }

    // epilogue: mean over channels; warp dj owns flattened d = dj*7 + di
    const float invC = 1.0f / (float)C_;
    const int y = y0 + tyl;
    const int x = x0 + xl;
#pragma unroll
    for (int d = 0; d < 7; ++d) {
        float r[8];
#pragma unroll
        for (int pp = 0; pp < 4; ++pp)
            unpack2(r[pp * 2], r[pp * 2 + 1], acc2[d * 4 + pp]);
        float* op = out + (((size_t)b * ND + dj * 7 + d) * H_ + y) * W_ + x;
        float4 o0, o1;
        o0.x = r[0] * invC; o0.y = r[1] * invC;
        o0.z = r[2] * invC; o0.w = r[3] * invC;
        o1.x = r[4] * invC; o1.y = r[5] * invC;
        o1.z = r[6] * invC; o1.w = r[7] * invC;
        ((float4*)op)[0] = o0;
        ((float4*)op)[1] = o1;
    }
}

extern "C" void kernel_launch(void* const* d_in, const int* in_sizes, int n_in,
                              void* d_out, int out_size)
{
    const float* first  = (const float*)d_in[0];
    const float* second = (const float*)d_in[1];
    float* out = (float*)d_out;

    cudaFuncSetAttribute(corr_kernel,
                         cudaFuncAttributeMaxDynamicSharedMemorySize,
                         (int)SMEM_BYTES);

    dim3 grid(W_ / TX, H_ / TY, B_);   // 14 x 24 x 8 = 2688 CTAs
    dim3 block(NT);
    corr_kernel<<<grid, block, SMEM_BYTES>>>(first, second, out);
}